// round 2
// baseline (speedup 1.0000x reference)
#include <cuda_runtime.h>
#include <cuda_bf16.h>

// NCAM3D: B=512, C1=16, C2=30, P=15  -> x viewed as (512, 480, 15, 15) fp32
// gate[b,c] = sigmoid(2*a1*a2 - 0.4), where a1/a2 are sigmoid of K=5 channel
// convs over per-channel full means / center-3x3 means (+ reversed-channel row).
// out = x * gate (broadcast over 15x15).

#define NB   512
#define NC   480
#define NHW  225          // 15*15
#define CHF  (NC * NHW)   // 108000 floats per batch

__device__ __forceinline__ float fsigmoid(float x) {
    return 1.0f / (1.0f + __expf(-x));
}

__global__ __launch_bounds__(512) void ncam3d_kernel(
    const float* __restrict__ x,
    const float* __restrict__ w1, const float* __restrict__ b1,
    const float* __restrict__ w2, const float* __restrict__ b2,
    float* __restrict__ out)
{
    __shared__ float s_full[NC];
    __shared__ float s_cent[NC];
    __shared__ float s_gate[NC];

    const int b    = blockIdx.x;
    const int tid  = threadIdx.x;
    const int wid  = tid >> 5;
    const int lane = tid & 31;

    const float* __restrict__ xb = x + (size_t)b * CHF;

    // ---------------- Pass 1: per-channel reductions (warp per channel) ----
    for (int c = wid; c < NC; c += 16) {
        const float* __restrict__ p = xb + c * NHW;
        float fs = 0.0f, cs = 0.0f;
        #pragma unroll
        for (int k = 0; k < 8; k++) {
            int i = lane + 32 * k;
            if (i < NHW) {
                float v = p[i];
                fs += v;
                // center 3x3: linear indices {96..98, 111..113, 126..128}
                unsigned r = (unsigned)(i - 96);
                if ((r < 3u) || ((r - 15u) < 3u) || ((r - 30u) < 3u)) cs += v;
            }
        }
        #pragma unroll
        for (int o = 16; o > 0; o >>= 1) {
            fs += __shfl_xor_sync(0xffffffffu, fs, o);
            cs += __shfl_xor_sync(0xffffffffu, cs, o);
        }
        if (lane == 0) { s_full[c] = fs; s_cent[c] = cs; }
    }
    __syncthreads();

    // ---------------- Gate stage: dual-row K=5 conv + sigmoids -------------
    if (tid < NC) {
        const int c = tid;
        const float inv = 1.0f / 225.0f;
        float acc1 = __ldg(b1);
        float acc2 = __ldg(b2);
        #pragma unroll
        for (int k = 0; k < 5; k++) {
            int j = c + k - 2;
            if (j >= 0 && j < NC) {
                // row 0: means at channel j ; row 1: means at reversed channel
                float f1 = s_full[j]          * inv;
                float f2 = s_full[NC - 1 - j] * inv;
                float c1 = s_cent[j]          * inv;
                float c2 = s_cent[NC - 1 - j] * inv;
                acc1 += __ldg(w1 + k) * f1 + __ldg(w1 + 5 + k) * f2;
                acc2 += __ldg(w2 + k) * c1 + __ldg(w2 + 5 + k) * c2;
            }
        }
        float a1 = fsigmoid(acc1);
        float a2 = fsigmoid(acc2);
        s_gate[c] = fsigmoid(2.0f * (a1 * a2) - 0.4f);
    }
    __syncthreads();

    // ---------------- Pass 2: gated copy, float4-vectorized ----------------
    // 108000 floats per batch = 27000 float4 (batch base is 16B-aligned:
    // 432000 bytes per batch).
    const float4* __restrict__ xv = (const float4*)xb;
    float4* __restrict__ ov = (float4*)(out + (size_t)b * CHF);
    for (int i = tid; i < CHF / 4; i += 512) {
        float4 v = xv[i];
        int e = i << 2;
        v.x *= s_gate[(e    ) / NHW];
        v.y *= s_gate[(e + 1) / NHW];
        v.z *= s_gate[(e + 2) / NHW];
        v.w *= s_gate[(e + 3) / NHW];
        ov[i] = v;
    }
}

extern "C" void kernel_launch(void* const* d_in, const int* in_sizes, int n_in,
                              void* d_out, int out_size) {
    const float* x  = (const float*)d_in[0];
    const float* w1 = (const float*)d_in[1];
    const float* b1 = (const float*)d_in[2];
    const float* w2 = (const float*)d_in[3];
    const float* b2 = (const float*)d_in[4];
    float* out = (float*)d_out;

    ncam3d_kernel<<<NB, 512>>>(x, w1, b1, w2, b2, out);
}